// round 3
// baseline (speedup 1.0000x reference)
#include <cuda_runtime.h>
#include <stdint.h>

#define BB 256
#define TT 32768
#define KK 3
#define ALPHA 0.95f
#define THETA 0.05f
// prevfloat(0.05f): v > THETA_M  <=>  v >= THETA
#define THETA_M __uint_as_float(0x3D4CCCCCu)
#define LCH 512          // chunk length
#define NCH (TT / LCH)   // 64 chunks
#define PF 16            // prefetch depth (steps)

// scratch: u transposed [k][t][b] (+ prefetch overrun pad), spike bitmasks [k][g][t]
__device__ float    g_uS[KK * TT * BB + PF * BB];
__device__ uint32_t g_sbits[KK * 8 * TT];

// ---------------------------------------------------------------------------
// Kernel 1: causal convs. Tile = 32 b x 32 t. Writes u to d_out ([b][k][t])
// and to g_uS ([k][t][b]), both coalesced via smem staging.
// ---------------------------------------------------------------------------
__global__ void conv_kernel(const float* __restrict__ x,
                            const float* __restrict__ w8,
                            const float* __restrict__ w16,
                            const float* __restrict__ w32,
                            float* __restrict__ u_out) {
    __shared__ float xs[32][65];      // 32 b x 63 t (padded, conflict-free)
    __shared__ float us[3][32][37];   // staged results, pad 37 (coprime 32)
    __shared__ float wf[64];          // flipped weights: [0:32)=w32, [32:48)=w16, [48:56)=w8

    const int tid    = threadIdx.x;                  // 256 threads
    const int tile_t = blockIdx.x * 32;
    const int b0     = blockIdx.y * 32;

    if (tid < 32)       wf[tid] = w32[31 - tid];
    else if (tid < 48)  wf[tid] = w16[15 - (tid - 32)];
    else if (tid < 56)  wf[tid] = w8[7 - (tid - 48)];

    for (int i = tid; i < 32 * 63; i += 256) {
        int bl = i / 63, j = i % 63;
        int t  = tile_t - 31 + j;
        xs[bl][j] = (t >= 0) ? x[(size_t)(b0 + bl) * TT + t] : 0.0f;
    }
    __syncthreads();

    const int bl = tid & 31;
    const int tq = (tid >> 5) * 4;   // first of 4 consecutive t's
    float win[35];
#pragma unroll
    for (int i = 0; i < 35; i++) win[i] = xs[bl][tq + i];

    float a32[4] = {0, 0, 0, 0}, a16[4] = {0, 0, 0, 0}, a8[4] = {0, 0, 0, 0};
#pragma unroll
    for (int d = 0; d < 32; d++) {
        float wv = wf[d];
#pragma unroll
        for (int j = 0; j < 4; j++) a32[j] = fmaf(wv, win[31 + j - d], a32[j]);
    }
#pragma unroll
    for (int d = 0; d < 16; d++) {
        float wv = wf[32 + d];
#pragma unroll
        for (int j = 0; j < 4; j++) a16[j] = fmaf(wv, win[31 + j - d], a16[j]);
    }
#pragma unroll
    for (int d = 0; d < 8; d++) {
        float wv = wf[48 + d];
#pragma unroll
        for (int j = 0; j < 4; j++) a8[j] = fmaf(wv, win[31 + j - d], a8[j]);
    }
#pragma unroll
    for (int j = 0; j < 4; j++) {
        us[0][bl][tq + j] = a8[j];
        us[1][bl][tq + j] = a16[j];
        us[2][bl][tq + j] = a32[j];
    }
    __syncthreads();

    // phase 1: u_out [b][k][t], 768 float4
    for (int f = tid; f < 768; f += 256) {
        int t4 = f & 7;
        int r  = f >> 3;          // r = bb*3 + k
        int k  = r % 3, bb = r / 3;
        float4 v;
        v.x = us[k][bb][t4 * 4 + 0];
        v.y = us[k][bb][t4 * 4 + 1];
        v.z = us[k][bb][t4 * 4 + 2];
        v.w = us[k][bb][t4 * 4 + 3];
        *(float4*)&u_out[((size_t)(b0 + bb) * 3 + k) * TT + tile_t + t4 * 4] = v;
    }
    // phase 2: g_uS [k][t][b], coalesced over b (lane = b)
    for (int f = tid; f < 96 * 32; f += 256) {
        int bl2 = f & 31;
        int row = f >> 5;         // 0..95
        int k   = row >> 5;
        int tl  = row & 31;
        g_uS[(k * TT + tile_t + tl) * BB + b0 + bl2] = us[k][bl2][tl];
    }
}

// ---------------------------------------------------------------------------
// Kernel 2: chunked WTA-LIF scan. 16384 threads: thread n -> (b = n&255,
// chunk c = n>>8). Warp = 32 consecutive b, same chunk. Warmup W = 512 from
// v=0 (exact for c<=1, synchronized for c>=2). Spikes -> ballot bitmasks.
// ---------------------------------------------------------------------------
__device__ __forceinline__ void lif_step(float& v0, float& v1, float& v2,
                                         float u0, float u1, float u2,
                                         bool& s0, bool& s1, bool& s2) {
    v0 = fmaf(ALPHA, v0, u0);
    v1 = fmaf(ALPHA, v1, u1);
    v2 = fmaf(ALPHA, v2, u2);
    // winner-take-all with first-index tie-break, spike iff winner >= theta
    s0 = (v0 >= fmaxf(v1, THETA)) & (v0 >= v2);
    s1 = (v1 > v0) & (v1 >= fmaxf(v2, THETA));
    s2 = (v2 > v0) & (v2 > fmaxf(v1, THETA_M));
    float w0 = v0 - THETA, w1 = v1 - THETA, w2 = v2 - THETA;
    v0 = s0 ? w0 : v0;
    v1 = s1 ? w1 : v1;
    v2 = s2 ? w2 : v2;
}

__global__ void __launch_bounds__(128, 1) scan_kernel() {
    const int n = blockIdx.x * 128 + threadIdx.x;   // 128 blocks x 128
    const int b = n & (BB - 1);
    const int c = n >> 8;
    const int out_t0 = c * LCH;
    const int t0 = (c == 0) ? 0 : out_t0 - LCH;
    const int nw = out_t0 - t0;                     // warmup steps (0 or 512)
    const int PL = TT * BB;

    const float* p = g_uS + (size_t)t0 * BB + b;
    float q0[PF], q1[PF], q2[PF];
#pragma unroll
    for (int i = 0; i < PF; i++) {
        q0[i] = __ldg(p + i * BB);
        q1[i] = __ldg(p + PL + i * BB);
        q2[i] = __ldg(p + 2 * PL + i * BB);
    }

    float v0 = 0.f, v1 = 0.f, v2 = 0.f;
    bool s0, s1, s2;

    for (int g = 0; g < nw; g += PF) {
#pragma unroll
        for (int i = 0; i < PF; i++) {
            float u0 = q0[i], u1 = q1[i], u2 = q2[i];
            q0[i] = __ldg(p + (i + PF) * BB);
            q1[i] = __ldg(p + PL + (i + PF) * BB);
            q2[i] = __ldg(p + 2 * PL + (i + PF) * BB);
            lif_step(v0, v1, v2, u0, u1, u2, s0, s1, s2);
        }
        p += PF * BB;
    }

    uint32_t* sp = g_sbits + (uint32_t)(b >> 5) * TT + out_t0;
    const bool lead = ((threadIdx.x & 31) == 0);
    for (int g = 0; g < LCH; g += PF) {
#pragma unroll
        for (int i = 0; i < PF; i++) {
            float u0 = q0[i], u1 = q1[i], u2 = q2[i];
            q0[i] = __ldg(p + (i + PF) * BB);
            q1[i] = __ldg(p + PL + (i + PF) * BB);
            q2[i] = __ldg(p + 2 * PL + (i + PF) * BB);
            lif_step(v0, v1, v2, u0, u1, u2, s0, s1, s2);
            unsigned m0 = __ballot_sync(0xffffffffu, s0);
            unsigned m1 = __ballot_sync(0xffffffffu, s1);
            unsigned m2 = __ballot_sync(0xffffffffu, s2);
            if (lead) {
                sp[g + i]           = m0;
                sp[8 * TT + g + i]  = m1;
                sp[16 * TT + g + i] = m2;
            }
        }
        p += PF * BB;
    }
}

// ---------------------------------------------------------------------------
// Kernel 3: expand bitmasks -> float s [b][k][t]
// ---------------------------------------------------------------------------
__global__ void expand_kernel(float* __restrict__ out_s) {
    const int i  = blockIdx.x * 256 + threadIdx.x;   // B*K*T/4 threads
    const int t4 = i & (TT / 4 - 1);
    const int r  = i >> 13;          // r = b*3 + k, < 768
    const int k  = r % 3;
    const int b  = r / 3;
    const uint4 w = *(const uint4*)(g_sbits + ((size_t)(k * 8 + (b >> 5)) * TT) + t4 * 4);
    const int bit = b & 31;
    float4 o;
    o.x = (float)((w.x >> bit) & 1u);
    o.y = (float)((w.y >> bit) & 1u);
    o.z = (float)((w.z >> bit) & 1u);
    o.w = (float)((w.w >> bit) & 1u);
    *(float4*)(out_s + (size_t)r * TT + t4 * 4) = o;
}

// ---------------------------------------------------------------------------
extern "C" void kernel_launch(void* const* d_in, const int* in_sizes, int n_in,
                              void* d_out, int out_size) {
    const float* x   = (const float*)d_in[0];
    // d_in[1] = y, unused by the reference outputs
    const float* w8  = (const float*)d_in[2];
    const float* w16 = (const float*)d_in[3];
    const float* w32 = (const float*)d_in[4];
    float* out = (float*)d_out;

    conv_kernel<<<dim3(TT / 32, BB / 32), 256>>>(x, w8, w16, w32, out);
    scan_kernel<<<NCH * 2, 128>>>();
    expand_kernel<<<(BB * KK * TT / 4) / 256, 256>>>(out + (size_t)BB * KK * TT);
}

// round 4
// speedup vs baseline: 1.5070x; 1.5070x over previous
#include <cuda_runtime.h>
#include <stdint.h>

#define BB 256
#define TT 32768
#define KK 3
#define ALPHA 0.95f
#define THETA 0.05f
// prevfloat(0.05f): v > THETA_M  <=>  v >= THETA
#define THETA_M __uint_as_float(0x3D4CCCCCu)
#define LCH 256          // chunk length
#define NCH (TT / LCH)   // 128 chunks
#define WMAX 512         // max warmup steps
#define PF 16            // prefetch depth (steps)

// scratch: u transposed [k][t][b] (+ prefetch overrun pad)
__device__ float g_uS[KK * TT * BB + PF * BB];

// ---------------------------------------------------------------------------
// Kernel 1: causal convs. Tile = 32 b x 64 t, 256 threads, 8 outputs/thread.
// smem union: xs (input tile) then reused as us (staged results, pad 69 so
// (69*bl + c) % 32 = (5*bl + c) % 32 -> conflict-free on every access pattern).
// FMA accumulation order identical to the validated R3 kernel (bit-identical u).
// ---------------------------------------------------------------------------
__global__ void __launch_bounds__(256) conv_kernel(const float* __restrict__ x,
                                                   const float* __restrict__ w8,
                                                   const float* __restrict__ w16,
                                                   const float* __restrict__ w32,
                                                   float* __restrict__ u_out) {
    __shared__ float wf[64];   // flipped weights: [0:32)=w32, [32:48)=w16, [48:56)=w8
    __shared__ __align__(16) float buf[KK * 32 * 69];   // 26496 B, unioned
    float (*xs)[97]     = reinterpret_cast<float (*)[97]>(buf);      // 32 x 97 = 12416 B
    float (*us)[32][69] = reinterpret_cast<float (*)[32][69]>(buf);  // 3 x 32 x 69

    const int tid    = threadIdx.x;
    const int w      = tid >> 5;          // warp 0..7
    const int l      = tid & 31;          // lane
    const int tile_t = blockIdx.x * 64;
    const int b0     = blockIdx.y * 32;

    if (tid < 32)       wf[tid] = w32[31 - tid];
    else if (tid < 48)  wf[tid] = w16[47 - tid];
    else if (tid < 56)  wf[tid] = w8[55 - tid];

    // ---- phase A: load xs[r][c] = x[b0+r][tile_t-32+c], c in [0,96) ----
#pragma unroll
    for (int rr = 0; rr < 4; rr++) {
        int r = w + rr * 8;
        const float* xr = x + (size_t)(b0 + r) * TT + tile_t - 32;
#pragma unroll
        for (int cc = 0; cc < 3; cc++) {
            int c = cc * 32 + l;
            xs[r][c] = (tile_t - 32 + c >= 0) ? xr[c] : 0.0f;
        }
    }
    __syncthreads();

    // ---- phase B: each thread computes 8 outputs (t = tile_t + tq + j) ----
    const int bl = l;
    const int tq = w * 8;
    float win[39];
#pragma unroll
    for (int i = 0; i < 39; i++) win[i] = xs[bl][tq + 1 + i];   // win[i] = x[t0 + i - 31]
    __syncthreads();   // xs dead; us may now overwrite the union

    float a32[8] = {0,0,0,0,0,0,0,0}, a16[8] = {0,0,0,0,0,0,0,0}, a8[8] = {0,0,0,0,0,0,0,0};
#pragma unroll
    for (int d = 0; d < 32; d++) {
        float wv = wf[d];
#pragma unroll
        for (int j = 0; j < 8; j++) a32[j] = fmaf(wv, win[31 + j - d], a32[j]);
    }
#pragma unroll
    for (int d = 0; d < 16; d++) {
        float wv = wf[32 + d];
#pragma unroll
        for (int j = 0; j < 8; j++) a16[j] = fmaf(wv, win[31 + j - d], a16[j]);
    }
#pragma unroll
    for (int d = 0; d < 8; d++) {
        float wv = wf[48 + d];
#pragma unroll
        for (int j = 0; j < 8; j++) a8[j] = fmaf(wv, win[31 + j - d], a8[j]);
    }
#pragma unroll
    for (int j = 0; j < 8; j++) {
        us[0][bl][tq + j] = a8[j];
        us[1][bl][tq + j] = a16[j];
        us[2][bl][tq + j] = a32[j];
    }
    __syncthreads();

    // ---- phase D: u_out [b][k][t] (warp writes 128B rows) ----
#pragma unroll
    for (int bbq = 0; bbq < 4; bbq++) {
        int bb = w * 4 + bbq;
        float* orow = u_out + (size_t)(b0 + bb) * 3 * TT + tile_t;
#pragma unroll
        for (int k = 0; k < 3; k++)
#pragma unroll
            for (int h = 0; h < 2; h++)
                orow[(size_t)k * TT + 32 * h + l] = us[k][bb][32 * h + l];
    }
    // ---- phase E: g_uS [k][t][b] (lane = b, 128B rows) ----
#pragma unroll
    for (int j = 0; j < 24; j++) {
        int r  = w * 24 + j;        // 0..191
        int k  = r >> 6;
        int tl = r & 63;
        g_uS[((size_t)k * TT + tile_t + tl) * BB + b0 + l] = us[k][l][tl];
    }
}

// ---------------------------------------------------------------------------
// Kernel 2: chunked WTA-LIF scan + fused spike expansion.
// 256 blocks x 128 threads; block -> (chunk c = blk>>1, b0s = (blk&1)*128).
// Warmup t0 = max(0, c*LCH - WMAX): exact for c<=2, synchronized (err ~2e-12)
// for c>=3. Ballot bitmasks staged in smem, expanded to float at chunk end.
// ---------------------------------------------------------------------------
__device__ __forceinline__ void lif_step(float& v0, float& v1, float& v2,
                                         float u0, float u1, float u2,
                                         bool& s0, bool& s1, bool& s2) {
    v0 = fmaf(ALPHA, v0, u0);
    v1 = fmaf(ALPHA, v1, u1);
    v2 = fmaf(ALPHA, v2, u2);
    // winner-take-all, argmax first-index tie-break, spike iff winner >= theta
    s0 = (v0 >= fmaxf(v1, THETA)) & (v0 >= v2);
    s1 = (v1 > v0) & (v1 >= fmaxf(v2, THETA));
    s2 = (v2 > v0) & (v2 > fmaxf(v1, THETA_M));
    float w0 = v0 - THETA, w1 = v1 - THETA, w2 = v2 - THETA;
    v0 = s0 ? w0 : v0;
    v1 = s1 ? w1 : v1;
    v2 = s2 ? w2 : v2;
}

__global__ void __launch_bounds__(128, 1) scan_kernel(float* __restrict__ out_s) {
    __shared__ uint32_t sb[KK][4][LCH];   // spike bitmasks [k][warp][t], 12 KB

    const int tid    = threadIdx.x;
    const int wid    = tid >> 5;
    const int b0s    = (blockIdx.x & 1) * 128;
    const int c      = blockIdx.x >> 1;
    const int b      = b0s + tid;
    const int out_t0 = c * LCH;
    const int t0     = (out_t0 > WMAX) ? (out_t0 - WMAX) : 0;
    const int nw     = out_t0 - t0;      // warmup steps (0, 256, or 512)
    const int PL     = TT * BB;

    const float* p = g_uS + (size_t)t0 * BB + b;
    float q0[PF], q1[PF], q2[PF];
#pragma unroll
    for (int i = 0; i < PF; i++) {
        q0[i] = __ldg(p + i * BB);
        q1[i] = __ldg(p + PL + i * BB);
        q2[i] = __ldg(p + 2 * PL + i * BB);
    }

    float v0 = 0.f, v1 = 0.f, v2 = 0.f;
    bool s0, s1, s2;

    for (int g = 0; g < nw; g += PF) {
#pragma unroll
        for (int i = 0; i < PF; i++) {
            float u0 = q0[i], u1 = q1[i], u2 = q2[i];
            q0[i] = __ldg(p + (i + PF) * BB);
            q1[i] = __ldg(p + PL + (i + PF) * BB);
            q2[i] = __ldg(p + 2 * PL + (i + PF) * BB);
            lif_step(v0, v1, v2, u0, u1, u2, s0, s1, s2);
        }
        p += PF * BB;
    }

    const bool lead = ((tid & 31) == 0);
    for (int g = 0; g < LCH; g += PF) {
#pragma unroll
        for (int i = 0; i < PF; i++) {
            float u0 = q0[i], u1 = q1[i], u2 = q2[i];
            q0[i] = __ldg(p + (i + PF) * BB);
            q1[i] = __ldg(p + PL + (i + PF) * BB);
            q2[i] = __ldg(p + 2 * PL + (i + PF) * BB);
            lif_step(v0, v1, v2, u0, u1, u2, s0, s1, s2);
            unsigned m0 = __ballot_sync(0xffffffffu, s0);
            unsigned m1 = __ballot_sync(0xffffffffu, s1);
            unsigned m2 = __ballot_sync(0xffffffffu, s2);
            if (lead) {
                sb[0][wid][g + i] = m0;
                sb[1][wid][g + i] = m1;
                sb[2][wid][g + i] = m2;
            }
        }
        p += PF * BB;
    }
    __syncthreads();

    // ---- fused expansion: 128 b x 3 k x 256 t floats for this block ----
    // rows r = bq*3 + k (matches out layout), 64 float4 per row.
    for (int f = tid; f < 128 * 3 * (LCH / 4); f += 128) {
        int t4 = f & (LCH / 4 - 1);
        int r  = f >> 6;
        int bq = r / 3;
        int k  = r - bq * 3;
        uint4 wbits = *(const uint4*)&sb[k][bq >> 5][t4 * 4];
        int bit = bq & 31;
        float4 o;
        o.x = (float)((wbits.x >> bit) & 1u);
        o.y = (float)((wbits.y >> bit) & 1u);
        o.z = (float)((wbits.z >> bit) & 1u);
        o.w = (float)((wbits.w >> bit) & 1u);
        *(float4*)(out_s + ((size_t)(b0s + bq) * 3 + k) * TT + out_t0 + t4 * 4) = o;
    }
}

// ---------------------------------------------------------------------------
extern "C" void kernel_launch(void* const* d_in, const int* in_sizes, int n_in,
                              void* d_out, int out_size) {
    const float* x   = (const float*)d_in[0];
    // d_in[1] = y, unused by the reference outputs
    const float* w8  = (const float*)d_in[2];
    const float* w16 = (const float*)d_in[3];
    const float* w32 = (const float*)d_in[4];
    float* out = (float*)d_out;

    conv_kernel<<<dim3(TT / 64, BB / 32), 256>>>(x, w8, w16, w32, out);
    scan_kernel<<<NCH * 2, 128>>>(out + (size_t)BB * KK * TT);
}